// round 11
// baseline (speedup 1.0000x reference)
#include <cuda_runtime.h>
#include <math.h>

#define DIM       512
#define NBLK      592          // = 4 * 148 SMs: one balanced wave, 64 warps/SM
#define THREADS_X 128          // float4 lanes covering DIM
#define THREADS_Y 4
#define NGRP      16           // completion hierarchy: 592 = 16 * 37
#define GRP_SZ    37

// Level-1 partials: per (block, dim-pair) float4 {P0,Q0,P1,Q1}. 592*256*16B = 2.4 MB.
__device__ float4 g_scratch[NBLK * (DIM / 2)];
// Level-2 partials: 16 * 256 * 16B = 64 KB.
__device__ float4 g_scratch2[NGRP * (DIM / 2)];
// Completion counters (zero-initialized at load; reset by final block each run).
__device__ int g_cnt_grp[NGRP];
__device__ int g_cnt_fin;

// ---------------------------------------------------------------------------
// Fused kernel. Inner loop deliberately matches R6's codegen (the 71.4%-DRAM
// configuration): PLAIN float4 global loads (no __ldcs) + unroll 8 +
// computed-index addressing. Only the grid (balanced single wave) and the
// fused in-kernel finish differ from R6.
//
// Closed form per dim d (s = pv - pc):
//   sum_t log(2*pi*var_t)        = T*log2pi + (T-1)*log(s) + log(s + T*pc)
//   sum_t (z_t-mu_t)^2 / var_t   = (Q - pc/(s+T*pc) * P^2) / s
// with P = Sz - T*mu0, Q = Szz - 2*mu0*Sz + T*mu0^2.
// c0 = -0.5 * T * log(2pi), host double.
// ---------------------------------------------------------------------------
__global__ void __launch_bounds__(THREADS_X * THREADS_Y)
k_fused(const float* __restrict__ z,
        const float* __restrict__ var_vbl,
        const float* __restrict__ corr_vbl,
        const float* __restrict__ prior_mu,
        float* __restrict__ out,
        int T, float c0) {
    const int x   = threadIdx.x;                  // 0..127
    const int y   = threadIdx.y;                  // 0..3
    const int tid = y * THREADS_X + x;
    const int b   = blockIdx.x;

    // ---- Phase 1: streaming partial reduction -----------------------------
    // Row-groups of 4 rows (one per y). Total groups = T/4 = 16384.
    // 16384 = 400*28 + 192*27: first 400 blocks take 28 groups, rest 27.
    const int base_cnt = 16384 / NBLK;            // 27
    const int rem      = 16384 % NBLK;            // 400
    const int g0    = b * base_cnt + (b < rem ? b : rem);
    const int iters = base_cnt + (b < rem ? 1 : 0);

    const float4* __restrict__ zp = reinterpret_cast<const float4*>(z);

    float4 P = make_float4(0.f, 0.f, 0.f, 0.f);
    float4 Q = make_float4(0.f, 0.f, 0.f, 0.f);

    const long long row0 = (long long)g0 * THREADS_Y + y;

    #pragma unroll 8
    for (int i = 0; i < iters; ++i) {
        float4 v = zp[(row0 + (long long)i * THREADS_Y) * (DIM / 4) + x];
        P.x += v.x; P.y += v.y; P.z += v.z; P.w += v.w;
        Q.x = fmaf(v.x, v.x, Q.x);
        Q.y = fmaf(v.y, v.y, Q.y);
        Q.z = fmaf(v.z, v.z, Q.z);
        Q.w = fmaf(v.w, v.w, Q.w);
    }

    __shared__ float4 sP[THREADS_Y][THREADS_X];
    __shared__ float4 sQ[THREADS_Y][THREADS_X];
    sP[y][x] = P;
    sQ[y][x] = Q;
    __syncthreads();

    if (y == 0) {
        float4 p = sP[0][x];
        float4 q = sQ[0][x];
        #pragma unroll
        for (int j = 1; j < THREADS_Y; ++j) {
            float4 pj = sP[j][x];
            float4 qj = sQ[j][x];
            p.x += pj.x; p.y += pj.y; p.z += pj.z; p.w += pj.w;
            q.x += qj.x; q.y += qj.y; q.z += qj.z; q.w += qj.w;
        }
        float4* __restrict__ outp = &g_scratch[b * (DIM / 2) + 2 * x];
        outp[0] = make_float4(p.x, q.x, p.y, q.y);
        outp[1] = make_float4(p.z, q.z, p.w, q.w);
        __threadfence();   // partials visible before the counter bump
    }
    __syncthreads();

    // ---- Phase 2: last block of each 37-block group reduces the group -----
    __shared__ int s_flag;
    const int grp = b / GRP_SZ;                   // 0..15
    if (tid == 0) {
        int done = atomicAdd(&g_cnt_grp[grp], 1);
        s_flag = (done == GRP_SZ - 1);
    }
    __syncthreads();
    if (!s_flag) return;

    __threadfence();                               // acquire partials
    if (tid < DIM / 2) {
        const float4* __restrict__ sc = &g_scratch[grp * GRP_SZ * (DIM / 2)];
        float4 acc = make_float4(0.f, 0.f, 0.f, 0.f);
        #pragma unroll 8
        for (int r = 0; r < GRP_SZ; ++r) {
            float4 v = sc[r * (DIM / 2) + tid];
            acc.x += v.x; acc.y += v.y; acc.z += v.z; acc.w += v.w;
        }
        g_scratch2[grp * (DIM / 2) + tid] = acc;
        __threadfence();
    }
    __syncthreads();

    // ---- Phase 3: last group-leader does the final reduce + epilogue ------
    __shared__ int s_fin;
    if (tid == 0) {
        int done = atomicAdd(&g_cnt_fin, 1);
        s_fin = (done == NGRP - 1);
    }
    __syncthreads();
    if (!s_fin) return;

    __threadfence();                               // acquire level-2 partials
    __shared__ float red[DIM / 2];
    const int j = tid;                             // dim-pair 0..255
    if (j < DIM / 2) {
        float4 acc = make_float4(0.f, 0.f, 0.f, 0.f);
        #pragma unroll
        for (int g = 0; g < NGRP; ++g) {
            float4 v = g_scratch2[g * (DIM / 2) + j];
            acc.x += v.x; acc.y += v.y; acc.z += v.z; acc.w += v.w;
        }

        const float Tn = (float)T;
        float lkd_pair = 0.f;
        #pragma unroll
        for (int w = 0; w < 2; ++w) {
            const int d = 2 * j + w;
            const float Sz  = w ? acc.z : acc.x;
            const float Szz = w ? acc.w : acc.y;

            const float x1  = var_vbl[d];
            const float x2  = corr_vbl[d];
            const float mu0 = prior_mu[d];

            const float sp = (x1 > 20.0f) ? x1 : log1pf(expf(x1));
            const float pv = sp * sp;
            const float sg = 1.0f / (1.0f + expf(-x2));
            const float pc = sg * pv;
            const float s  = pv - pc;

            const float Pd = Sz - Tn * mu0;
            const float Qd = Szz - 2.0f * mu0 * Sz + Tn * mu0 * mu0;

            const float denom = s + Tn * pc;
            const float quad  = (Qd - (pc / denom) * Pd * Pd) / s;

            lkd_pair += c0 - 0.5f * ((Tn - 1.0f) * logf(s) + logf(denom) + quad);
        }
        red[j] = lkd_pair;
    }
    __syncthreads();

    #pragma unroll
    for (int off = DIM / 4; off > 0; off >>= 1) {
        if (j < off) red[j] += red[j + off];
        __syncthreads();
    }

    if (tid == 0) out[0] = red[0];

    // Reset counters for next graph replay (safe: g_cnt_fin reached NGRP only
    // after every block bumped its group counter).
    if (tid < NGRP) g_cnt_grp[tid] = 0;
    if (tid == NGRP) g_cnt_fin = 0;
}

// ---------------------------------------------------------------------------
extern "C" void kernel_launch(void* const* d_in, const int* in_sizes, int n_in,
                              void* d_out, int out_size) {
    const float* z_rest   = (const float*)d_in[0];   // [T, 512]
    const float* var_vbl  = (const float*)d_in[1];   // [512]
    const float* corr_vbl = (const float*)d_in[2];   // [512]
    const float* prior_mu = (const float*)d_in[3];   // [512]
    float* out = (float*)d_out;

    const int T = in_sizes[0] / DIM;                 // 65536

    const double LOG_2PI = 1.8378770664093454835606594728112;
    const float c0 = (float)(-0.5 * (double)T * LOG_2PI);

    dim3 blk(THREADS_X, THREADS_Y);
    k_fused<<<NBLK, blk>>>(z_rest, var_vbl, corr_vbl, prior_mu, out, T, c0);
}

// round 12
// speedup vs baseline: 1.2378x; 1.2378x over previous
#include <cuda_runtime.h>
#include <math.h>

#define DIM       512
#define NBLK      512          // k1 grid: 32 regs * 512 thr -> 4 blocks/SM, single wave
#define THREADS_X 128          // float4 lanes covering DIM
#define THREADS_Y 4
#define NTAIL     16           // tail grid; 512 = 16 * 32 rows per tail block

// Level-1 partials: per (k1-block, dim-pair) float4 {P0,Q0,P1,Q1}. 512*256*16B = 2 MB.
__device__ float4 g_scratch[NBLK * (DIM / 2)];
// Level-2 partials: 16 * 256 * 16B = 64 KB.
__device__ float4 g_scratch2[NTAIL * (DIM / 2)];
// Completion counter (zero-initialized at load; reset by final tail block).
__device__ int g_cnt_fin;

// ---------------------------------------------------------------------------
// Kernel 1 — EXACT R6 configuration (the 71.4%-DRAM / 5.65 TB/s streaming
// loop): standalone, plain float4 loads, unroll 8, computed index, uniform
// 128 rows per block. Do not add tail logic here: fused variants measured
// 3.5-4.2 TB/s on the identical loop.
// ---------------------------------------------------------------------------
__global__ void __launch_bounds__(THREADS_X * THREADS_Y)
k1_reduce(const float* __restrict__ z, int rows_per_blk) {
    const int x = threadIdx.x;        // 0..127 : float4 lane -> dims 4x..4x+3
    const int y = threadIdx.y;        // 0..3   : row interleave
    const int b = blockIdx.x;

    const float4* __restrict__ zp = reinterpret_cast<const float4*>(z);

    float4 P = make_float4(0.f, 0.f, 0.f, 0.f);
    float4 Q = make_float4(0.f, 0.f, 0.f, 0.f);

    const long long row0 = (long long)b * rows_per_blk + y;
    const int iters = rows_per_blk / THREADS_Y;   // 32

    #pragma unroll 8
    for (int i = 0; i < iters; ++i) {
        float4 v = zp[(row0 + (long long)i * THREADS_Y) * (DIM / 4) + x];
        P.x += v.x; P.y += v.y; P.z += v.z; P.w += v.w;
        Q.x = fmaf(v.x, v.x, Q.x);
        Q.y = fmaf(v.y, v.y, Q.y);
        Q.z = fmaf(v.z, v.z, Q.z);
        Q.w = fmaf(v.w, v.w, Q.w);
    }

    __shared__ float4 sP[THREADS_Y][THREADS_X];
    __shared__ float4 sQ[THREADS_Y][THREADS_X];
    sP[y][x] = P;
    sQ[y][x] = Q;
    __syncthreads();

    if (y == 0) {
        float4 p = sP[0][x];
        float4 q = sQ[0][x];
        #pragma unroll
        for (int j = 1; j < THREADS_Y; ++j) {
            float4 pj = sP[j][x];
            float4 qj = sQ[j][x];
            p.x += pj.x; p.y += pj.y; p.z += pj.z; p.w += pj.w;
            q.x += qj.x; q.y += qj.y; q.z += qj.z; q.w += qj.w;
        }
        float4* __restrict__ outp = &g_scratch[b * (DIM / 2) + 2 * x];
        outp[0] = make_float4(p.x, q.x, p.y, q.y);
        outp[1] = make_float4(p.z, q.z, p.w, q.w);
    }
}

// ---------------------------------------------------------------------------
// Tail kernel — single launch, two reduction levels via last-block election.
// Each of 16 blocks reduces 32 partial rows (256 KB/block... L2-resident);
// the last-arriving block reduces the 16 level-2 rows and runs the fp32
// closed-form epilogue:
//   per dim d (s = pv - pc):
//   sum_t log(2*pi*var_t)      = T*log2pi + (T-1)*log(s) + log(s + T*pc)
//   sum_t (z_t-mu_t)^2 / var_t = (Q - pc/(s+T*pc) * P^2) / s
//   P = Sz - T*mu0, Q = Szz - 2*mu0*Sz + T*mu0^2;  c0 = -0.5*T*log2pi (host).
// ---------------------------------------------------------------------------
__global__ void __launch_bounds__(DIM / 2)
k_tail(const float* __restrict__ var_vbl,
       const float* __restrict__ corr_vbl,
       const float* __restrict__ prior_mu,
       float* __restrict__ out,
       int T, float c0) {
    const int j = threadIdx.x;            // dim-pair 0..255 -> dims 2j, 2j+1
    const int g = blockIdx.x;             // 0..15
    const int rows = NBLK / NTAIL;        // 32

    // ---- Level 1: reduce this block's 32 rows -----------------------------
    const float4* __restrict__ sc = g_scratch;
    float4 acc = make_float4(0.f, 0.f, 0.f, 0.f);
    #pragma unroll 8
    for (int r = 0; r < rows; ++r) {
        float4 v = sc[(g * rows + r) * (DIM / 2) + j];
        acc.x += v.x; acc.y += v.y; acc.z += v.z; acc.w += v.w;
    }
    g_scratch2[g * (DIM / 2) + j] = acc;
    __threadfence();
    __syncthreads();

    // ---- Elect last block -------------------------------------------------
    __shared__ int s_fin;
    if (j == 0) {
        int done = atomicAdd(&g_cnt_fin, 1);
        s_fin = (done == NTAIL - 1);
    }
    __syncthreads();
    if (!s_fin) return;

    __threadfence();                       // acquire level-2 partials

    // ---- Level 2 + epilogue ----------------------------------------------
    float4 a2 = make_float4(0.f, 0.f, 0.f, 0.f);
    #pragma unroll
    for (int r = 0; r < NTAIL; ++r) {
        float4 v = g_scratch2[r * (DIM / 2) + j];
        a2.x += v.x; a2.y += v.y; a2.z += v.z; a2.w += v.w;
    }

    const float Tn = (float)T;
    float lkd_pair = 0.f;
    #pragma unroll
    for (int w = 0; w < 2; ++w) {
        const int d = 2 * j + w;
        const float Sz  = w ? a2.z : a2.x;
        const float Szz = w ? a2.w : a2.y;

        const float x1  = var_vbl[d];
        const float x2  = corr_vbl[d];
        const float mu0 = prior_mu[d];

        const float sp = (x1 > 20.0f) ? x1 : log1pf(expf(x1));
        const float pv = sp * sp;
        const float sg = 1.0f / (1.0f + expf(-x2));
        const float pc = sg * pv;
        const float s  = pv - pc;

        const float Pd = Sz - Tn * mu0;
        const float Qd = Szz - 2.0f * mu0 * Sz + Tn * mu0 * mu0;

        const float denom = s + Tn * pc;
        const float quad  = (Qd - (pc / denom) * Pd * Pd) / s;

        lkd_pair += c0 - 0.5f * ((Tn - 1.0f) * logf(s) + logf(denom) + quad);
    }

    __shared__ float red[DIM / 2];
    red[j] = lkd_pair;
    __syncthreads();
    #pragma unroll
    for (int off = DIM / 4; off > 0; off >>= 1) {
        if (j < off) red[j] += red[j + off];
        __syncthreads();
    }

    if (j == 0) {
        out[0] = red[0];
        g_cnt_fin = 0;     // reset for next graph replay (all blocks arrived)
    }
}

// ---------------------------------------------------------------------------
extern "C" void kernel_launch(void* const* d_in, const int* in_sizes, int n_in,
                              void* d_out, int out_size) {
    const float* z_rest   = (const float*)d_in[0];   // [T, 512]
    const float* var_vbl  = (const float*)d_in[1];   // [512]
    const float* corr_vbl = (const float*)d_in[2];   // [512]
    const float* prior_mu = (const float*)d_in[3];   // [512]
    float* out = (float*)d_out;

    const int T = in_sizes[0] / DIM;                 // 65536
    const int rows_per_blk = T / NBLK;               // 128

    const double LOG_2PI = 1.8378770664093454835606594728112;
    const float c0 = (float)(-0.5 * (double)T * LOG_2PI);

    dim3 blk1(THREADS_X, THREADS_Y);
    k1_reduce<<<NBLK, blk1>>>(z_rest, rows_per_blk);
    k_tail<<<NTAIL, DIM / 2>>>(var_vbl, corr_vbl, prior_mu, out, T, c0);
}

// round 13
// speedup vs baseline: 1.3265x; 1.0716x over previous
#include <cuda_runtime.h>
#include <math.h>

#define DIM       512
#define NBLK      512          // k1 grid: 32 regs * 512 thr -> 4 blocks/SM, single wave
#define THREADS_X 128          // float4 lanes covering DIM
#define THREADS_Y 4
#define NTAIL     32           // tail grid
#define NPAIR     (DIM / 2)    // 256 dim-pairs

// Level-1 partials: per (k1-block, dim-pair) float4 {P0,Q0,P1,Q1}. 512*256*16B = 2 MB.
__device__ float4 g_scratch[NBLK * NPAIR];
// Level-2 partials: 32 * 256 * 16B = 128 KB.
__device__ float4 g_scratch2[NTAIL * NPAIR];
// Completion counter (zero-initialized at load; reset by final tail block).
__device__ int g_cnt_fin;

// ---------------------------------------------------------------------------
// Kernel 1 — EXACT R6 configuration (the 71.4%-DRAM / 5.65 TB/s streaming
// loop): standalone, plain float4 loads, unroll 8, computed index, uniform
// 128 rows per block. Do not add tail logic here: fused variants measured
// 3.5-4.2 TB/s on the identical loop.
// ---------------------------------------------------------------------------
__global__ void __launch_bounds__(THREADS_X * THREADS_Y)
k1_reduce(const float* __restrict__ z, int rows_per_blk) {
    const int x = threadIdx.x;        // 0..127 : float4 lane -> dims 4x..4x+3
    const int y = threadIdx.y;        // 0..3   : row interleave
    const int b = blockIdx.x;

    const float4* __restrict__ zp = reinterpret_cast<const float4*>(z);

    float4 P = make_float4(0.f, 0.f, 0.f, 0.f);
    float4 Q = make_float4(0.f, 0.f, 0.f, 0.f);

    const long long row0 = (long long)b * rows_per_blk + y;
    const int iters = rows_per_blk / THREADS_Y;   // 32

    #pragma unroll 8
    for (int i = 0; i < iters; ++i) {
        float4 v = zp[(row0 + (long long)i * THREADS_Y) * (DIM / 4) + x];
        P.x += v.x; P.y += v.y; P.z += v.z; P.w += v.w;
        Q.x = fmaf(v.x, v.x, Q.x);
        Q.y = fmaf(v.y, v.y, Q.y);
        Q.z = fmaf(v.z, v.z, Q.z);
        Q.w = fmaf(v.w, v.w, Q.w);
    }

    __shared__ float4 sP[THREADS_Y][THREADS_X];
    __shared__ float4 sQ[THREADS_Y][THREADS_X];
    sP[y][x] = P;
    sQ[y][x] = Q;
    __syncthreads();

    if (y == 0) {
        float4 p = sP[0][x];
        float4 q = sQ[0][x];
        #pragma unroll
        for (int j = 1; j < THREADS_Y; ++j) {
            float4 pj = sP[j][x];
            float4 qj = sQ[j][x];
            p.x += pj.x; p.y += pj.y; p.z += pj.z; p.w += pj.w;
            q.x += qj.x; q.y += qj.y; q.z += qj.z; q.w += qj.w;
        }
        float4* __restrict__ outp = &g_scratch[b * NPAIR + 2 * x];
        outp[0] = make_float4(p.x, q.x, p.y, q.y);
        outp[1] = make_float4(p.z, q.z, p.w, q.w);
    }
}

// ---------------------------------------------------------------------------
// Tail kernel — high-MLP version. The partials are DRAM-resident (the z
// stream evicted them from L2), so level 1 needs many warps AND explicitly
// batched independent loads (previous 32-reg version serialized to ~1
// outstanding load/warp -> 173 GB/s -> 12 us).
//
// 32 blocks x 1024 threads: j = dim-pair (0..255), sl = row-slice (0..3).
// Level 1: each block reduces 16 partial rows (4 per slice, batched x4),
//          smem slice-combine, write one level-2 row.
// Level 2: last-elected block reduces the 32 level-2 rows (L2-hot, batched
//          x8), then the fp32 closed-form epilogue:
//   per dim d (s = pv - pc):
//   sum_t log(2*pi*var_t)      = T*log2pi + (T-1)*log(s) + log(s + T*pc)
//   sum_t (z_t-mu_t)^2 / var_t = (Q - pc/(s+T*pc) * P^2) / s
//   P = Sz - T*mu0, Q = Szz - 2*mu0*Sz + T*mu0^2;  c0 = -0.5*T*log2pi (host).
// ---------------------------------------------------------------------------
__global__ void __launch_bounds__(1024)
k_tail(const float* __restrict__ var_vbl,
       const float* __restrict__ corr_vbl,
       const float* __restrict__ prior_mu,
       float* __restrict__ out,
       int T, float c0) {
    const int tid = threadIdx.x;          // 0..1023
    const int j   = tid & (NPAIR - 1);    // dim-pair 0..255 -> dims 2j, 2j+1
    const int sl  = tid >> 8;             // row-slice 0..3
    const int g   = blockIdx.x;           // 0..31

    __shared__ float4 s1[4][NPAIR];       // 16 KB slice-combine buffer

    // ---- Level 1: 16 rows per block, 4 per slice, batched loads -----------
    {
        const float4* __restrict__ base =
            &g_scratch[(g * 16 + sl * 4) * NPAIR + j];
        float4 v0 = base[0 * NPAIR];
        float4 v1 = base[1 * NPAIR];
        float4 v2 = base[2 * NPAIR];
        float4 v3 = base[3 * NPAIR];
        float4 a;
        a.x = (v0.x + v1.x) + (v2.x + v3.x);
        a.y = (v0.y + v1.y) + (v2.y + v3.y);
        a.z = (v0.z + v1.z) + (v2.z + v3.z);
        a.w = (v0.w + v1.w) + (v2.w + v3.w);
        s1[sl][j] = a;
    }
    __syncthreads();

    if (sl == 0) {
        float4 a = s1[0][j], b1 = s1[1][j], b2 = s1[2][j], b3 = s1[3][j];
        a.x = (a.x + b1.x) + (b2.x + b3.x);
        a.y = (a.y + b1.y) + (b2.y + b3.y);
        a.z = (a.z + b1.z) + (b2.z + b3.z);
        a.w = (a.w + b1.w) + (b2.w + b3.w);
        g_scratch2[g * NPAIR + j] = a;
    }
    __threadfence();
    __syncthreads();

    // ---- Elect last block -------------------------------------------------
    __shared__ int s_fin;
    if (tid == 0) {
        int done = atomicAdd(&g_cnt_fin, 1);
        s_fin = (done == NTAIL - 1);
    }
    __syncthreads();
    if (!s_fin) return;

    __threadfence();                       // acquire level-2 partials

    // ---- Level 2: 32 rows, 8 per slice, batched loads (L2-hot) ------------
    {
        const float4* __restrict__ base = &g_scratch2[(sl * 8) * NPAIR + j];
        float4 v0 = base[0 * NPAIR];
        float4 v1 = base[1 * NPAIR];
        float4 v2 = base[2 * NPAIR];
        float4 v3 = base[3 * NPAIR];
        float4 v4 = base[4 * NPAIR];
        float4 v5 = base[5 * NPAIR];
        float4 v6 = base[6 * NPAIR];
        float4 v7 = base[7 * NPAIR];
        float4 a;
        a.x = ((v0.x + v1.x) + (v2.x + v3.x)) + ((v4.x + v5.x) + (v6.x + v7.x));
        a.y = ((v0.y + v1.y) + (v2.y + v3.y)) + ((v4.y + v5.y) + (v6.y + v7.y));
        a.z = ((v0.z + v1.z) + (v2.z + v3.z)) + ((v4.z + v5.z) + (v6.z + v7.z));
        a.w = ((v0.w + v1.w) + (v2.w + v3.w)) + ((v4.w + v5.w) + (v6.w + v7.w));
        s1[sl][j] = a;
    }
    __syncthreads();

    __shared__ float red[NPAIR];
    if (sl == 0) {
        float4 a = s1[0][j], b1 = s1[1][j], b2 = s1[2][j], b3 = s1[3][j];
        a.x = (a.x + b1.x) + (b2.x + b3.x);
        a.y = (a.y + b1.y) + (b2.y + b3.y);
        a.z = (a.z + b1.z) + (b2.z + b3.z);
        a.w = (a.w + b1.w) + (b2.w + b3.w);

        // ---- Epilogue (fp32 closed form) ---------------------------------
        const float Tn = (float)T;
        float lkd_pair = 0.f;
        #pragma unroll
        for (int w = 0; w < 2; ++w) {
            const int d = 2 * j + w;
            const float Sz  = w ? a.z : a.x;
            const float Szz = w ? a.w : a.y;

            const float x1  = var_vbl[d];
            const float x2  = corr_vbl[d];
            const float mu0 = prior_mu[d];

            const float sp = (x1 > 20.0f) ? x1 : log1pf(expf(x1));
            const float pv = sp * sp;
            const float sg = 1.0f / (1.0f + expf(-x2));
            const float pc = sg * pv;
            const float s  = pv - pc;

            const float Pd = Sz - Tn * mu0;
            const float Qd = Szz - 2.0f * mu0 * Sz + Tn * mu0 * mu0;

            const float denom = s + Tn * pc;
            const float quad  = (Qd - (pc / denom) * Pd * Pd) / s;

            lkd_pair += c0 - 0.5f * ((Tn - 1.0f) * logf(s) + logf(denom) + quad);
        }
        red[j] = lkd_pair;
    }
    __syncthreads();

    #pragma unroll
    for (int off = NPAIR / 2; off > 0; off >>= 1) {
        if (tid < off) red[tid] += red[tid + off];
        __syncthreads();
    }

    if (tid == 0) {
        out[0] = red[0];
        g_cnt_fin = 0;     // reset for next graph replay (all blocks arrived)
    }
}

// ---------------------------------------------------------------------------
extern "C" void kernel_launch(void* const* d_in, const int* in_sizes, int n_in,
                              void* d_out, int out_size) {
    const float* z_rest   = (const float*)d_in[0];   // [T, 512]
    const float* var_vbl  = (const float*)d_in[1];   // [512]
    const float* corr_vbl = (const float*)d_in[2];   // [512]
    const float* prior_mu = (const float*)d_in[3];   // [512]
    float* out = (float*)d_out;

    const int T = in_sizes[0] / DIM;                 // 65536
    const int rows_per_blk = T / NBLK;               // 128

    const double LOG_2PI = 1.8378770664093454835606594728112;
    const float c0 = (float)(-0.5 * (double)T * LOG_2PI);

    dim3 blk1(THREADS_X, THREADS_Y);
    k1_reduce<<<NBLK, blk1>>>(z_rest, rows_per_blk);
    k_tail<<<NTAIL, 1024>>>(var_vbl, corr_vbl, prior_mu, out, T, c0);
}